// round 10
// baseline (speedup 1.0000x reference)
#include <cuda_runtime.h>
#include <cuda_fp16.h>
#include <stdint.h>

// ---------------- Problem dims ----------------
#define B_DIM  4096
#define N_IN   1024
#define N_HID  4096
#define N_OUT  1024

// ---------------- GEMM tiling ----------------
#define BM 128
#define BN 256
#define BK 64                  // k elems per stage
#define SLOTS 4                // smem slots; 3 in flight
#define NTHR 256
#define A_BYTES (BM * 128)     // 16384  (128 m-rows x 128B)
#define B_BYTES (BK * 512)     // 32768  (64 k-rows x 512B of n)
#define STG (A_BYTES + B_BYTES)        // 49152
#define SMEM_G (SLOTS * STG)           // 196608 -> 1 CTA/SM

// ---------------- Device scratch (allocation-free rule) ----------------
__device__ __align__(128) __half g_xf[(size_t)B_DIM * N_IN];
__device__ __align__(128) __half g_w1[(size_t)N_IN * N_HID];    // [K][N] fp16
__device__ __align__(128) __half g_w2[(size_t)N_HID * N_OUT];   // [K][N] fp16
__device__ __align__(128) __half g_hf[(size_t)B_DIM * N_HID];

// ---------------- PTX helpers ----------------
__device__ __forceinline__ uint32_t smem_u32(const void* p) {
    uint32_t a;
    asm("{ .reg .u64 t; cvta.to.shared.u64 t, %1; cvt.u32.u64 %0, t; }" : "=r"(a) : "l"(p));
    return a;
}
#define CP_ASYNC16(dst, src) \
    asm volatile("cp.async.cg.shared.global [%0], [%1], 16;" :: "r"(dst), "l"(src))
#define CP_COMMIT() asm volatile("cp.async.commit_group;" ::: "memory")
#define CP_WAIT2()  asm volatile("cp.async.wait_group 2;" ::: "memory")

#define LDSM4(r0, r1, r2, r3, a) \
    asm volatile("ldmatrix.sync.aligned.m8n8.x4.shared.b16 {%0,%1,%2,%3}, [%4];" \
                 : "=r"(r0), "=r"(r1), "=r"(r2), "=r"(r3) : "r"(a))
#define LDSM4T(r0, r1, r2, r3, a) \
    asm volatile("ldmatrix.sync.aligned.m8n8.x4.trans.shared.b16 {%0,%1,%2,%3}, [%4];" \
                 : "=r"(r0), "=r"(r1), "=r"(r2), "=r"(r3) : "r"(a))

__device__ __forceinline__ void mma16816(float* d, const uint32_t* a, uint32_t b0, uint32_t b1) {
    asm volatile(
        "mma.sync.aligned.m16n8k16.row.col.f32.f16.f16.f32 "
        "{%0,%1,%2,%3}, {%4,%5,%6,%7}, {%8,%9}, {%0,%1,%2,%3};\n"
        : "+f"(d[0]), "+f"(d[1]), "+f"(d[2]), "+f"(d[3])
        : "r"(a[0]), "r"(a[1]), "r"(a[2]), "r"(a[3]), "r"(b0), "r"(b1));
}

// ---------------- Convert kernel (elementwise fp32 -> fp16) ----------------
__global__ __launch_bounds__(256) void cvt_f16(const float* __restrict__ in,
                                               __half* __restrict__ out) {
    size_t g = (size_t)(blockIdx.x * 256 + threadIdx.x) * 8;
    float4 v0 = *reinterpret_cast<const float4*>(in + g);
    float4 v1 = *reinterpret_cast<const float4*>(in + g + 4);
    float vv[8] = {v0.x, v0.y, v0.z, v0.w, v1.x, v1.y, v1.z, v1.w};
    union { unsigned short us[8]; uint4 q; } p;
#pragma unroll
    for (int j = 0; j < 8; ++j) p.us[j] = __half_as_ushort(__float2half_rn(vv[j]));
    *reinterpret_cast<uint4*>(out + g) = p.q;
}

// ---------------- GEMM: C = act(A @ W + bias) ----------------
// A: [M][K] fp16 row-major (128B k-rows, xor swizzle, normal ldmatrix).
// W: [K][N] fp16 row-major; 64 k-rows x 512B tiles, xor swizzle per 128B group,
//    read with ldmatrix.x4.trans.
// CTA 128x256, 8 warps (2M x 4N), warp tile 64x64 (MMA:LDSM4 ratio 4.0);
// 1 CTA/SM, 4-slot / 3-deep cp.async pipeline, one __syncthreads per k-tile.
template <bool RELU, bool F16_OUT>
__global__ __launch_bounds__(NTHR, 1) void gemm_f16(
    const __half* __restrict__ A, const __half* __restrict__ Bw,
    const float* __restrict__ bias,
    float* __restrict__ Y, __half* __restrict__ Oh,
    int N, int K)
{
    constexpr int MT = 4;     // m16 tiles per warp (64 rows)
    constexpr int NT = 8;     // n8 tiles per warp (64 cols)
    constexpr int NG = 4;     // n16 ldmatrix groups per warp

    extern __shared__ __align__(1024) char smem[];
    const uint32_t sb = smem_u32(smem);
    const int tid  = threadIdx.x;
    const int lane = tid & 31;
    const int warp = tid >> 5;
    const int warp_m = (warp & 1) * 64;    // 2 warps along M
    const int warp_n = (warp >> 1) * 64;   // 4 warps along N
    const int m0 = blockIdx.y * BM;
    const int n0 = blockIdx.x * BN;

    // A-frag lane coords (normal ldmatrix from [M][K])
    const int fr  = lane & 15;
    const int fch = lane >> 4;
    // B-frag lane coords (trans ldmatrix from [K][N])
    const int bj   = lane >> 3;            // matrix index 0..3
    const int bi   = lane & 7;
    const int bk0  = (bj & 1) * 8 + bi;    // k-row base within k16 step
    const int cn0  = (warp_n >> 3) + (bj >> 1);  // 16B chunk base in 512B row

    float acc[MT][NT][4];
#pragma unroll
    for (int mt = 0; mt < MT; ++mt)
#pragma unroll
        for (int nt = 0; nt < NT; ++nt)
#pragma unroll
            for (int i = 0; i < 4; ++i) acc[mt][nt][i] = 0.f;

    const int ntiles = K >> 6;

    auto prefetch = [&](int s, int kt) {
        const uint32_t stg = sb + s * STG;
        const int kof = kt * 64;
        // A tile: 128 rows x 8 chunks (16B), xor swizzle within 128B rows
#pragma unroll
        for (int i = 0; i < 4; ++i) {
            int idx = tid + i * NTHR;
            int r = idx >> 3, ch = idx & 7;
            uint32_t soff = (uint32_t)r * 128 + (uint32_t)((ch ^ (r & 7)) * 16);
            CP_ASYNC16(stg + soff, (const char*)(A + (size_t)(m0 + r) * K + kof + ch * 8));
        }
        // B tile: 64 k-rows x 32 chunks (16B) = 512B/row, xor swizzle per 128B group
#pragma unroll
        for (int i = 0; i < 8; ++i) {
            int idx = tid + i * NTHR;
            int r = idx >> 5, c = idx & 31;
            uint32_t soff = A_BYTES + (uint32_t)r * 512 +
                            (uint32_t)(((c & 24) | ((c ^ r) & 7)) * 16);
            CP_ASYNC16(stg + soff,
                       (const char*)(Bw + (size_t)(kof + r) * N + n0 + c * 8));
        }
    };

    // 3 stages in flight
#pragma unroll
    for (int s = 0; s < 3; ++s) {
        if (s < ntiles) prefetch(s, s);
        CP_COMMIT();
    }

    // precomputed A fragment row offsets
    uint32_t ra128[MT], ramask[MT];
#pragma unroll
    for (int mt = 0; mt < MT; ++mt) {
        int r = warp_m + mt * 16 + fr;
        ra128[mt] = (uint32_t)r * 128;
        ramask[mt] = (uint32_t)(r & 7);
    }

    for (int kt = 0; kt < ntiles; ++kt) {
        const int s = kt & (SLOTS - 1);
        const uint32_t abase = sb + s * STG;
        const uint32_t bbase = abase + A_BYTES;

        CP_WAIT2();            // tile kt complete (3 in flight)
        __syncthreads();       // all warps done with iter kt-1 -> its slot refillable

        const int nk = kt + 3;
        if (nk < ntiles) prefetch(nk & (SLOTS - 1), nk);   // slot (kt-1)&3
        CP_COMMIT();

#pragma unroll
        for (int ks = 0; ks < 4; ++ks) {
            // A fragments
            const uint32_t chsel = (uint32_t)(ks * 2) + (uint32_t)fch;
            uint32_t af[MT][4];
#pragma unroll
            for (int mt = 0; mt < MT; ++mt) {
                uint32_t off = abase + ra128[mt] + ((chsel ^ ramask[mt]) * 16);
                LDSM4(af[mt][0], af[mt][1], af[mt][2], af[mt][3], off);
            }
            // B fragments (trans, k-major tile)
            const uint32_t kr = (uint32_t)(ks * 16 + bk0);
            uint32_t bf[NG][4];
#pragma unroll
            for (int ng = 0; ng < NG; ++ng) {
                uint32_t cn = (uint32_t)(cn0 + ng * 2);
                uint32_t off = bbase + kr * 512 + (((cn & 24) | ((cn ^ kr) & 7)) * 16);
                LDSM4T(bf[ng][0], bf[ng][1], bf[ng][2], bf[ng][3], off);
            }
#pragma unroll
            for (int mt = 0; mt < MT; ++mt) {
#pragma unroll
                for (int ng = 0; ng < NG; ++ng) {
                    mma16816(acc[mt][ng * 2],     af[mt], bf[ng][0], bf[ng][1]);
                    mma16816(acc[mt][ng * 2 + 1], af[mt], bf[ng][2], bf[ng][3]);
                }
            }
        }
    }

    // ---- epilogue ----
#pragma unroll
    for (int mt = 0; mt < MT; ++mt) {
#pragma unroll
        for (int nt = 0; nt < NT; ++nt) {
            const int r = m0 + warp_m + mt * 16 + (lane >> 2);
            const int c = n0 + warp_n + nt * 8 + (lane & 3) * 2;
            const float bb0 = __ldg(&bias[c]);
            const float bb1 = __ldg(&bias[c + 1]);
            float v0 = acc[mt][nt][0] + bb0;
            float v1 = acc[mt][nt][1] + bb1;
            float v2 = acc[mt][nt][2] + bb0;
            float v3 = acc[mt][nt][3] + bb1;
            if (RELU) {
                v0 = fmaxf(v0, 0.f); v1 = fmaxf(v1, 0.f);
                v2 = fmaxf(v2, 0.f); v3 = fmaxf(v3, 0.f);
            }
            if (F16_OUT) {
                *reinterpret_cast<__half2*>(Oh + (size_t)r * N + c) =
                    __floats2half2_rn(v0, v1);
                *reinterpret_cast<__half2*>(Oh + (size_t)(r + 8) * N + c) =
                    __floats2half2_rn(v2, v3);
            } else {
                *reinterpret_cast<float2*>(&Y[(size_t)r * N + c]) = make_float2(v0, v1);
                *reinterpret_cast<float2*>(&Y[(size_t)(r + 8) * N + c]) = make_float2(v2, v3);
            }
        }
    }
}

// ---------------- Host launch ----------------
extern "C" void kernel_launch(void* const* d_in, const int* in_sizes, int n_in,
                              void* d_out, int out_size) {
    const float* x  = (const float*)d_in[0];
    const float* W1 = (const float*)d_in[1];
    const float* b1 = (const float*)d_in[2];
    const float* W2 = (const float*)d_in[3];
    const float* b2 = (const float*)d_in[4];
    float* y = (float*)d_out;

    __half *xf, *w1, *w2, *hf;
    cudaGetSymbolAddress((void**)&xf, g_xf);
    cudaGetSymbolAddress((void**)&w1, g_w1);
    cudaGetSymbolAddress((void**)&w2, g_w2);
    cudaGetSymbolAddress((void**)&hf, g_hf);

    cudaFuncSetAttribute(gemm_f16<true, true>,
                         cudaFuncAttributeMaxDynamicSharedMemorySize, SMEM_G);
    cudaFuncSetAttribute(gemm_f16<false, false>,
                         cudaFuncAttributeMaxDynamicSharedMemorySize, SMEM_G);

    // Elementwise converts only (GEMM consumes [K][N] weights directly)
    cvt_f16<<<(B_DIM * N_IN / 8) / 256, 256>>>(x, xf);
    cvt_f16<<<((size_t)N_IN * N_HID / 8) / 256, 256>>>(W1, w1);
    cvt_f16<<<((size_t)N_HID * N_OUT / 8) / 256, 256>>>(W2, w2);

    // GEMM1: h = relu(x @ W1 + b1) -> fp16   (grid 16 x 32 = 512 CTAs)
    gemm_f16<true, true><<<dim3(N_HID / BN, B_DIM / BM), NTHR, SMEM_G>>>(
        xf, w1, b1, nullptr, hf, N_HID, N_IN);

    // GEMM2: y = h @ W2 + b2 (fp32 out)      (grid 4 x 32 = 128 CTAs, K=4096 deep)
    gemm_f16<false, false><<<dim3(N_OUT / BN, B_DIM / BM), NTHR, SMEM_G>>>(
        hf, w2, b2, y, nullptr, N_OUT, N_HID);
}

// round 11
// speedup vs baseline: 1.7563x; 1.7563x over previous
#include <cuda_runtime.h>
#include <cuda_fp16.h>
#include <stdint.h>

// ---------------- Problem dims ----------------
#define B_DIM  4096
#define N_IN   1024
#define N_HID  4096
#define N_OUT  1024

// ---------------- GEMM tiling ----------------
#define BM 128
#define BN 128
#define BK 64                  // k elems per stage
#define SLOTS 3                // smem slots; 2 in flight
#define NTHR 256
#define A_BYTES (BM * 128)     // 16384  (128 rows x 128B)
#define B_BYTES (BK * 256)     // 16384  (64 k-rows x 256B of n)
#define STG (A_BYTES + B_BYTES)
#define SMEM_G (SLOTS * STG)   // 96K -> 2 CTAs/SM

// ---------------- Device scratch (allocation-free rule) ----------------
__device__ __align__(128) __half g_xf[(size_t)B_DIM * N_IN];
__device__ __align__(128) __half g_w1[(size_t)N_IN * N_HID];    // [K][N] fp16
__device__ __align__(128) __half g_w2[(size_t)N_HID * N_OUT];   // [K][N] fp16
__device__ __align__(128) __half g_hf[(size_t)B_DIM * N_HID];

// ---------------- PTX helpers ----------------
__device__ __forceinline__ uint32_t smem_u32(const void* p) {
    uint32_t a;
    asm("{ .reg .u64 t; cvta.to.shared.u64 t, %1; cvt.u32.u64 %0, t; }" : "=r"(a) : "l"(p));
    return a;
}
#define CP_ASYNC16(dst, src) \
    asm volatile("cp.async.cg.shared.global [%0], [%1], 16;" :: "r"(dst), "l"(src))
#define CP_COMMIT() asm volatile("cp.async.commit_group;" ::: "memory")
#define CP_WAIT1()  asm volatile("cp.async.wait_group 1;" ::: "memory")

#define LDSM4(r0, r1, r2, r3, a) \
    asm volatile("ldmatrix.sync.aligned.m8n8.x4.shared.b16 {%0,%1,%2,%3}, [%4];" \
                 : "=r"(r0), "=r"(r1), "=r"(r2), "=r"(r3) : "r"(a))
#define LDSM4T(r0, r1, r2, r3, a) \
    asm volatile("ldmatrix.sync.aligned.m8n8.x4.trans.shared.b16 {%0,%1,%2,%3}, [%4];" \
                 : "=r"(r0), "=r"(r1), "=r"(r2), "=r"(r3) : "r"(a))

__device__ __forceinline__ void mma16816(float* d, const uint32_t* a, uint32_t b0, uint32_t b1) {
    asm volatile(
        "mma.sync.aligned.m16n8k16.row.col.f32.f16.f16.f32 "
        "{%0,%1,%2,%3}, {%4,%5,%6,%7}, {%8,%9}, {%0,%1,%2,%3};\n"
        : "+f"(d[0]), "+f"(d[1]), "+f"(d[2]), "+f"(d[3])
        : "r"(a[0]), "r"(a[1]), "r"(a[2]), "r"(a[3]), "r"(b0), "r"(b1));
}

// ---------------- Merged convert kernel ----------------
// All three fp32 tensors (x, W1, W2) are exactly 4194304 elements.
// One launch: 6144 CTAs; section = blockIdx.x >> 11 (2048 CTAs per tensor).
#define CVT_ELEMS   4194304
#define CVT_CTAS_PT 2048     // CTAs per tensor: 4194304 / (8*256)
__global__ __launch_bounds__(256) void cvt_all(const float* __restrict__ in0,
                                               const float* __restrict__ in1,
                                               const float* __restrict__ in2,
                                               __half* __restrict__ out0,
                                               __half* __restrict__ out1,
                                               __half* __restrict__ out2) {
    const int sec = blockIdx.x >> 11;
    const int cta = blockIdx.x & (CVT_CTAS_PT - 1);
    const float* in  = (sec == 0) ? in0  : (sec == 1) ? in1  : in2;
    __half*      out = (sec == 0) ? out0 : (sec == 1) ? out1 : out2;
    size_t g = (size_t)(cta * 256 + threadIdx.x) * 8;
    float4 v0 = *reinterpret_cast<const float4*>(in + g);
    float4 v1 = *reinterpret_cast<const float4*>(in + g + 4);
    float vv[8] = {v0.x, v0.y, v0.z, v0.w, v1.x, v1.y, v1.z, v1.w};
    union { unsigned short us[8]; uint4 q; } p;
#pragma unroll
    for (int j = 0; j < 8; ++j) p.us[j] = __half_as_ushort(__float2half_rn(vv[j]));
    *reinterpret_cast<uint4*>(out + g) = p.q;
}

// ---------------- GEMM: C = act(A @ W + bias) ----------------
// (identical to the verified round-9 kernel: 88us, tensor 64.5%)
// A: [M][K] fp16 row-major (128B k-rows in smem, xor swizzle, normal ldmatrix).
// W: [K][N] fp16 row-major; tiles of 64 k-rows x 256B staged in smem with
//    per-128B xor swizzle; read with ldmatrix.x4.trans -> col-major B frags.
// CTA 128x128, 8 warps (4 M x 2 N), warp tile 32x64; 2 CTAs/SM;
// 3-slot / 2-deep cp.async pipeline, one __syncthreads per k-tile.
template <bool RELU, bool F16_OUT>
__global__ __launch_bounds__(NTHR, 2) void gemm_f16(
    const __half* __restrict__ A, const __half* __restrict__ Bw,
    const float* __restrict__ bias,
    float* __restrict__ Y, __half* __restrict__ Oh,
    int N, int K)
{
    constexpr int NT = 8;     // n-tiles (n8) per warp
    constexpr int NG = 4;     // n16 ldmatrix groups per warp

    extern __shared__ __align__(1024) char smem[];
    const uint32_t sb = smem_u32(smem);
    const int tid  = threadIdx.x;
    const int lane = tid & 31;
    const int warp = tid >> 5;
    const int warp_m = (warp & 3) * 32;    // 4 warps along M
    const int warp_n = (warp >> 2) * 64;   // 2 warps along N
    const int m0 = blockIdx.y * BM;
    const int n0 = blockIdx.x * BN;

    // A-frag lane coords (normal ldmatrix from [M][K])
    const int fr  = lane & 15;
    const int fch = lane >> 4;
    // B-frag lane coords (trans ldmatrix from [K][N])
    const int bj   = lane >> 3;            // matrix index 0..3
    const int bi   = lane & 7;
    const int bk0  = (bj & 1) * 8 + bi;    // k-row base within k16 step
    const int cn0  = (warp_n >> 3) + (bj >> 1);  // 16B chunk base in 256B row

    float acc[2][NT][4];
#pragma unroll
    for (int mt = 0; mt < 2; ++mt)
#pragma unroll
        for (int nt = 0; nt < NT; ++nt)
#pragma unroll
            for (int i = 0; i < 4; ++i) acc[mt][nt][i] = 0.f;

    const int ntiles = K >> 6;

    auto prefetch = [&](int s, int kt) {
        const uint32_t stg = sb + s * STG;
        const int kof = kt * 64;
        // A tile: 128 rows x 8 chunks (16B), xor-swizzled in 128B rows
#pragma unroll
        for (int i = 0; i < 4; ++i) {
            int idx = tid + i * NTHR;
            int r = idx >> 3, ch = idx & 7;
            uint32_t soff = (uint32_t)r * 128 + (uint32_t)((ch ^ (r & 7)) * 16);
            CP_ASYNC16(stg + soff, (const char*)(A + (size_t)(m0 + r) * K + kof + ch * 8));
        }
        // B tile: 64 k-rows x 16 chunks (16B) = 256B/row, xor swizzle per 128B half
#pragma unroll
        for (int i = 0; i < 4; ++i) {
            int idx = tid + i * NTHR;
            int r = idx >> 4, c = idx & 15;
            uint32_t soff = A_BYTES + (uint32_t)r * 256 +
                            (uint32_t)(((c & 8) | ((c ^ r) & 7)) * 16);
            CP_ASYNC16(stg + soff,
                       (const char*)(Bw + (size_t)(kof + r) * N + n0 + c * 8));
        }
    };

    // 2 stages in flight
#pragma unroll
    for (int s = 0; s < 2; ++s) {
        if (s < ntiles) prefetch(s, s);
        CP_COMMIT();
    }

    // precomputed A fragment row offsets
    uint32_t ra128[2], ramask[2];
#pragma unroll
    for (int mt = 0; mt < 2; ++mt) {
        int r = warp_m + mt * 16 + fr;
        ra128[mt] = (uint32_t)r * 128;
        ramask[mt] = (uint32_t)(r & 7);
    }

    int s = 0;
    for (int kt = 0; kt < ntiles; ++kt) {
        const uint32_t abase = sb + s * STG;
        const uint32_t bbase = abase + A_BYTES;

        CP_WAIT1();            // tile kt complete (2 in flight)
        __syncthreads();       // all warps done with iter kt-1 -> its slot refillable

        const int nk = kt + 2;
        int ps = s + 2; if (ps >= SLOTS) ps -= SLOTS;   // slot of kt-1
        if (nk < ntiles) prefetch(ps, nk);
        CP_COMMIT();

#pragma unroll
        for (int ks = 0; ks < 4; ++ks) {
            // A fragments (normal ldmatrix)
            const uint32_t chsel = (uint32_t)(ks * 2) + (uint32_t)fch;
            uint32_t af[2][4];
#pragma unroll
            for (int mt = 0; mt < 2; ++mt) {
                uint32_t off = abase + ra128[mt] + ((chsel ^ ramask[mt]) * 16);
                LDSM4(af[mt][0], af[mt][1], af[mt][2], af[mt][3], off);
            }
            // B fragments (trans ldmatrix from k-major tile)
            const uint32_t kr = (uint32_t)(ks * 16 + bk0);
            uint32_t bf[NG][4];
#pragma unroll
            for (int ng = 0; ng < NG; ++ng) {
                uint32_t cn = (uint32_t)(cn0 + ng * 2);
                uint32_t off = bbase + kr * 256 + (((cn & 8) | ((cn ^ kr) & 7)) * 16);
                LDSM4T(bf[ng][0], bf[ng][1], bf[ng][2], bf[ng][3], off);
            }
#pragma unroll
            for (int mt = 0; mt < 2; ++mt) {
#pragma unroll
                for (int ng = 0; ng < NG; ++ng) {
                    mma16816(acc[mt][ng * 2],     af[mt], bf[ng][0], bf[ng][1]);
                    mma16816(acc[mt][ng * 2 + 1], af[mt], bf[ng][2], bf[ng][3]);
                }
            }
        }
        if (++s >= SLOTS) s = 0;
    }

    // ---- epilogue ----
#pragma unroll
    for (int mt = 0; mt < 2; ++mt) {
#pragma unroll
        for (int nt = 0; nt < NT; ++nt) {
            const int r = m0 + warp_m + mt * 16 + (lane >> 2);
            const int c = n0 + warp_n + nt * 8 + (lane & 3) * 2;
            const float bb0 = __ldg(&bias[c]);
            const float bb1 = __ldg(&bias[c + 1]);
            float v0 = acc[mt][nt][0] + bb0;
            float v1 = acc[mt][nt][1] + bb1;
            float v2 = acc[mt][nt][2] + bb0;
            float v3 = acc[mt][nt][3] + bb1;
            if (RELU) {
                v0 = fmaxf(v0, 0.f); v1 = fmaxf(v1, 0.f);
                v2 = fmaxf(v2, 0.f); v3 = fmaxf(v3, 0.f);
            }
            if (F16_OUT) {
                *reinterpret_cast<__half2*>(Oh + (size_t)r * N + c) =
                    __floats2half2_rn(v0, v1);
                *reinterpret_cast<__half2*>(Oh + (size_t)(r + 8) * N + c) =
                    __floats2half2_rn(v2, v3);
            } else {
                *reinterpret_cast<float2*>(&Y[(size_t)r * N + c]) = make_float2(v0, v1);
                *reinterpret_cast<float2*>(&Y[(size_t)(r + 8) * N + c]) = make_float2(v2, v3);
            }
        }
    }
}

// ---------------- Host launch ----------------
extern "C" void kernel_launch(void* const* d_in, const int* in_sizes, int n_in,
                              void* d_out, int out_size) {
    const float* x  = (const float*)d_in[0];
    const float* W1 = (const float*)d_in[1];
    const float* b1 = (const float*)d_in[2];
    const float* W2 = (const float*)d_in[3];
    const float* b2 = (const float*)d_in[4];
    float* y = (float*)d_out;

    __half *xf, *w1, *w2, *hf;
    cudaGetSymbolAddress((void**)&xf, g_xf);
    cudaGetSymbolAddress((void**)&w1, g_w1);
    cudaGetSymbolAddress((void**)&w2, g_w2);
    cudaGetSymbolAddress((void**)&hf, g_hf);

    cudaFuncSetAttribute(gemm_f16<true, true>,
                         cudaFuncAttributeMaxDynamicSharedMemorySize, SMEM_G);
    cudaFuncSetAttribute(gemm_f16<false, false>,
                         cudaFuncAttributeMaxDynamicSharedMemorySize, SMEM_G);

    // ONE merged convert launch for x, W1, W2 (all 4194304 elements each)
    cvt_all<<<3 * CVT_CTAS_PT, 256>>>(x, W1, W2, xf, w1, w2);

    // GEMM1: h = relu(x @ W1 + b1) -> fp16   (grid 32 x 32 = 1024 CTAs)
    gemm_f16<true, true><<<dim3(N_HID / BN, B_DIM / BM), NTHR, SMEM_G>>>(
        xf, w1, b1, nullptr, hf, N_HID, N_IN);

    // GEMM2: y = h @ W2 + b2 (fp32 out)      (grid 8 x 32 = 256 CTAs)
    gemm_f16<false, false><<<dim3(N_OUT / BN, B_DIM / BM), NTHR, SMEM_G>>>(
        hf, w2, b2, y, nullptr, N_OUT, N_HID);
}